// round 10
// baseline (speedup 1.0000x reference)
#include <cuda_runtime.h>

#define IMG 256
#define TW 64
#define TH 32
#define PR (TH + 6)   // 38 quartet-plane rows
#define CP (TW / 2)   // 32 column pairs

typedef unsigned long long u64;

// ---- packed f32x2 helpers (sm_103a FFMA2 path, PTX-only) ----
__device__ __forceinline__ u64 pk2(float lo, float hi) {
    u64 r; asm("mov.b64 %0, {%1,%2};" : "=l"(r) : "f"(lo), "f"(hi)); return r;
}
__device__ __forceinline__ void upk2(float& lo, float& hi, u64 p) {
    asm("mov.b64 {%0,%1}, %2;" : "=f"(lo), "=f"(hi) : "l"(p));
}
__device__ __forceinline__ u64 f2fma(u64 a, u64 b, u64 c) {
    u64 d; asm("fma.rn.f32x2 %0,%1,%2,%3;" : "=l"(d) : "l"(a), "l"(b), "l"(c)); return d;
}
__device__ __forceinline__ u64 f2mul(u64 a, u64 b) {
    u64 d; asm("mul.rn.f32x2 %0,%1,%2;" : "=l"(d) : "l"(a), "l"(b)); return d;
}
__device__ __forceinline__ u64 f2add(u64 a, u64 b) {
    u64 d; asm("add.rn.f32x2 %0,%1,%2;" : "=l"(d) : "l"(a), "l"(b)); return d;
}
__device__ __forceinline__ float ex2f(float x) {
    float r; asm("ex2.approx.f32 %0, %1;" : "=f"(r) : "f"(x)); return r;
}
__device__ __forceinline__ float rcpf(float x) {
    float r; asm("rcp.approx.f32 %0, %1;" : "=f"(r) : "f"(x)); return r;
}

__device__ __forceinline__ int reflect(int v) {
    v = (v < 0) ? -v : v;
    return (v > IMG - 1) ? 2 * (IMG - 1) - v : v;
}

__global__ __launch_bounds__(256, 4)
void AdaptiveGaussianFilter_66675072303489_kernel(
    const float* __restrict__ x,
    const float* __restrict__ sigma,
    float* __restrict__ out)
{
    // Pack-pair planes: qMA[r][cp] = {pack(m0,m1), pack(a0,a1)},
    //                   qBC[r][cp] = {pack(b0,b1), pack(c0,c1)}   (38.9 KB total)
    __shared__ __align__(16) u64 qMA[PR][CP][2];
    __shared__ __align__(16) u64 qBC[PR][CP][2];

    const int ch = blockIdx.z;
    const int x0 = blockIdx.x * TW;
    const int y0 = blockIdx.y * TH;

    const float* xc = x     + (size_t)ch * IMG * IMG;
    const float* sc = sigma + (size_t)ch * IMG * IMG;
    float*       oc = out   + (size_t)ch * IMG * IMG;

    const int tx  = threadIdx.x;             // colpair index 0..31
    const int ty  = threadIdx.y;
    const int tid = ty * 32 + tx;

    const int c2  = tx << 1;                 // column 0..62
    const int ly0 = ty << 2;                 // output row 0..28

    // Preload all 4 sigma pairs (latency hides under pass-1)
    const float* sp = sc + (y0 + ly0) * IMG + x0 + c2;
    u64 sg[4];
    sg[0] = *(const u64*)(sp);
    sg[1] = *(const u64*)(sp + IMG);
    sg[2] = *(const u64*)(sp + 2 * IMG);
    sg[3] = *(const u64*)(sp + 3 * IMG);

    // ---- Pass 1: build pack-pair planes straight from gmem ----
    const bool interior = (blockIdx.x != 0) & (blockIdx.x != 3) &
                          (blockIdx.y != 0) & (blockIdx.y != 7);
    #pragma unroll
    for (int it = 0; it < 3; it++) {
        int idx = tid + it * 256;
        if (idx < PR * 16) {                 // 38 rows x 16 strips of 4 cols
            int r   = idx >> 4;
            int c0  = (idx & 15) << 2;       // strip start col
            int cp0 = c0 >> 1;               // first colpair of strip
            float w[10];                     // x[x0+c0-3 .. x0+c0+6]
            if (interior) {
                const float* src = xc + (y0 + r - 3) * IMG + (x0 + c0 - 3);
                #pragma unroll
                for (int i = 0; i < 10; i++) w[i] = src[i];
            } else {
                const float* srow = xc + reflect(y0 + r - 3) * IMG;
                #pragma unroll
                for (int i = 0; i < 10; i++) w[i] = srow[reflect(x0 + c0 - 3 + i)];
            }
            // m=w0c, a=w-1+w+1, b=w-2+w+2, c=w-3+w+3, packed over col pairs
            ulonglong2 ma0, ma1, bc0, bc1;
            ma0.x = pk2(w[3],        w[4]);
            ma0.y = pk2(w[2] + w[4], w[3] + w[5]);
            ma1.x = pk2(w[5],        w[6]);
            ma1.y = pk2(w[4] + w[6], w[5] + w[7]);
            bc0.x = pk2(w[1] + w[5], w[2] + w[6]);
            bc0.y = pk2(w[0] + w[6], w[1] + w[7]);
            bc1.x = pk2(w[3] + w[7], w[4] + w[8]);
            bc1.y = pk2(w[2] + w[8], w[3] + w[9]);
            *(ulonglong2*)&qMA[r][cp0][0]     = ma0;
            *(ulonglong2*)&qMA[r][cp0 + 1][0] = ma1;
            *(ulonglong2*)&qBC[r][cp0][0]     = bc0;
            *(ulonglong2*)&qBC[r][cp0 + 1][0] = bc1;
        }
    }

    // ---- Pre-barrier: exp chains + normalizers (MUFU hidden under pass-1) ----
    const u64 NHL  = pk2(-0.72134752f, -0.72134752f);   // -0.5*log2(e)
    const u64 TWO2 = pk2(2.0f, 2.0f);
    const u64 ONE2 = pk2(1.0f, 1.0f);
    u64 t[4], t4[4], t9[4], inv2[4];
    #pragma unroll
    for (int k = 0; k < 4; k++) {
        u64 z = f2mul(sg[k], sg[k]);
        z = f2mul(z, NHL);
        float zl, zh; upk2(zl, zh, z);
        t[k]  = pk2(ex2f(zl), ex2f(zh));
        u64 t2 = f2mul(t[k], t[k]);
        t4[k] = f2mul(t2, t2);
        t9[k] = f2mul(f2mul(t4[k], t4[k]), t[k]);
        u64 S = f2fma(TWO2, f2add(f2add(t[k], t4[k]), t9[k]), ONE2);
        float sl, sh; upk2(sl, sh, S);
        u64 inv = pk2(rcpf(sl), rcpf(sh));   // 1/S
        inv2[k] = f2mul(inv, inv);           // 1/S^2
    }
    __syncthreads();

    // ---- Pass 2: stream 10 window rows; 4 packed accumulators ----
    u64 acc[4];
    #pragma unroll
    for (int w = -3; w <= 6; w++) {
        const int prow = ly0 + w + 3;        // 0..37
        ulonglong2 ma = *(const ulonglong2*)&qMA[prow][tx][0];
        ulonglong2 bc = *(const ulonglong2*)&qBC[prow][tx][0];
        #pragma unroll
        for (int k = 0; k < 4; k++) {
            const int d = (w > k) ? (w - k) : (k - w);
            if (d > 3) continue;
            u64 h = f2fma(t[k],  ma.y, ma.x);
            h     = f2fma(t4[k], bc.x, h);
            h     = f2fma(t9[k], bc.y, h);
            if (w == k - 3)     acc[k] = f2mul(t9[k], h);     // first contribution
            else if (d == 3)    acc[k] = f2fma(t9[k], h, acc[k]);
            else if (d == 2)    acc[k] = f2fma(t4[k], h, acc[k]);
            else if (d == 1)    acc[k] = f2fma(t[k],  h, acc[k]);
            else                acc[k] = f2add(acc[k], h);
        }
    }

    // ---- Epilogue: normalize (precomputed inv2) and store ----
    float* op = oc + (y0 + ly0) * IMG + x0 + c2;
    #pragma unroll
    for (int k = 0; k < 4; k++)
        *(u64*)(op + k * IMG) = f2mul(acc[k], inv2[k]);
}

extern "C" void kernel_launch(void* const* d_in, const int* in_sizes, int n_in,
                              void* d_out, int out_size)
{
    const float* x     = (const float*)d_in[0];
    const float* sigma = (const float*)d_in[1];
    float*       out   = (float*)d_out;

    dim3 block(32, 8, 1);
    dim3 grid(IMG / TW, IMG / TH, 16 * 3);   // 4 x 8 x 48 = 1536
    AdaptiveGaussianFilter_66675072303489_kernel<<<grid, block>>>(x, sigma, out);
}